// round 7
// baseline (speedup 1.0000x reference)
#include <cuda_runtime.h>
#include <cuda_bf16.h>
#include <cstdint>

// -(1/B) * sum(preds_t * log(preds_s)),  B = 4096, C = 1000  (n = 4,096,000)
// cp.async (LDGSTS) deep-prefetch reduction:
//   n_vec = 1,024,000 float4 = 1000 CTAs x (4 stages x 256 float4) per array.
//   Each thread issues 8 cp.async.cg (16B) up front -> 128B in flight/thread,
//   no registers consumed, no barriers in the main body (threads read back
//   only their own copies; wait_group gives per-thread visibility).

#define NTHR    256
#define NST     4                       // stages per CTA
#define NBLK_EX 1000
#define MAXBLK  2048

__device__ float g_partials[MAXBLK];
__device__ unsigned int g_ticket;       // zero-init; reset by last block each call

__device__ __forceinline__ uint32_t smem_u32(const void* p) {
    uint32_t a;
    asm("{ .reg .u64 t; cvta.to.shared.u64 t, %1; cvt.u32.u64 %0, t; }" : "=r"(a) : "l"(p));
    return a;
}

template <int N>
__device__ __forceinline__ void casync_wait_group() {
    asm volatile("cp.async.wait_group %0;" :: "n"(N) : "memory");
}

__device__ __forceinline__ float block_reduce(float acc, float* warp_sums)
{
    #pragma unroll
    for (int off = 16; off > 0; off >>= 1)
        acc += __shfl_xor_sync(0xFFFFFFFFu, acc, off);

    int lane = threadIdx.x & 31;
    int wid  = threadIdx.x >> 5;
    if (lane == 0) warp_sums[wid] = acc;
    __syncthreads();

    float v = 0.0f;
    if (wid == 0) {
        v = (lane < NTHR / 32) ? warp_sums[lane] : 0.0f;
        #pragma unroll
        for (int off = 4; off > 0; off >>= 1)
            v += __shfl_xor_sync(0xFFFFFFFFu, v, off);
    }
    return v;   // valid in warp 0 lane 0
}

__device__ __forceinline__ void finish(float acc, float inv_B, float* out, int nblk)
{
    __shared__ float warp_sums[NTHR / 32];
    float bsum = block_reduce(acc, warp_sums);

    __shared__ bool is_last;
    if (threadIdx.x == 0) {
        g_partials[blockIdx.x] = bsum;
        __threadfence();
        unsigned int ticket = atomicAdd(&g_ticket, 1u);
        is_last = (ticket == (unsigned int)(nblk - 1));
    }
    __syncthreads();

    if (is_last) {
        float a = 0.0f;
        for (int i = threadIdx.x; i < nblk; i += NTHR)
            a += g_partials[i];
        __syncthreads();
        float total = block_reduce(a, warp_sums);
        if (threadIdx.x == 0) {
            out[0] = -total * inv_B;
            g_ticket = 0;                   // reset for next graph replay
        }
    }
}

__global__ __launch_bounds__(NTHR) void casync_reduce(
    const float4* __restrict__ s4, const float4* __restrict__ t4,
    float inv_B, float* __restrict__ out)
{
    __shared__ alignas(16) float4 sbuf[NST][NTHR];
    __shared__ alignas(16) float4 tbuf[NST][NTHR];

    const int  tid  = threadIdx.x;
    const long base = (long)blockIdx.x * (NST * NTHR) + tid;

    // Prologue: issue all stage loads (8 x cp.async.cg 16B per thread),
    // one commit_group per stage.
    #pragma unroll
    for (int k = 0; k < NST; k++) {
        uint32_t ds = smem_u32(&sbuf[k][tid]);
        uint32_t dt = smem_u32(&tbuf[k][tid]);
        const float4* gs = s4 + base + (long)k * NTHR;
        const float4* gt = t4 + base + (long)k * NTHR;
        asm volatile(
            "cp.async.cg.shared.global [%0], [%1], 16;\n\t"
            "cp.async.cg.shared.global [%2], [%3], 16;\n\t"
            "cp.async.commit_group;"
            :: "r"(ds), "l"(gs), "r"(dt), "l"(gt) : "memory");
    }

    float acc = 0.0f;

    // Consume stages as their groups complete (per-thread visibility; no bar).
    {
        casync_wait_group<NST - 1>();
        float4 sv = sbuf[0][tid], tv = tbuf[0][tid];
        acc += tv.x * __logf(sv.x); acc += tv.y * __logf(sv.y);
        acc += tv.z * __logf(sv.z); acc += tv.w * __logf(sv.w);
    }
    {
        casync_wait_group<NST - 2>();
        float4 sv = sbuf[1][tid], tv = tbuf[1][tid];
        acc += tv.x * __logf(sv.x); acc += tv.y * __logf(sv.y);
        acc += tv.z * __logf(sv.z); acc += tv.w * __logf(sv.w);
    }
    {
        casync_wait_group<NST - 3>();
        float4 sv = sbuf[2][tid], tv = tbuf[2][tid];
        acc += tv.x * __logf(sv.x); acc += tv.y * __logf(sv.y);
        acc += tv.z * __logf(sv.z); acc += tv.w * __logf(sv.w);
    }
    {
        casync_wait_group<0>();
        float4 sv = sbuf[3][tid], tv = tbuf[3][tid];
        acc += tv.x * __logf(sv.x); acc += tv.y * __logf(sv.y);
        acc += tv.z * __logf(sv.z); acc += tv.w * __logf(sv.w);
    }

    finish(acc, inv_B, out, NBLK_EX);
}

// Generic fallback (any n), grid-stride. Only used if shape isn't exact-cover.
__global__ __launch_bounds__(NTHR) void fused_reduce_generic(
    const float* __restrict__ s, const float* __restrict__ t,
    int n, float inv_B, float* __restrict__ out, int nblk)
{
    int n_vec = n / 4;
    int tail0 = n_vec * 4;
    const float4* s4 = reinterpret_cast<const float4*>(s);
    const float4* t4 = reinterpret_cast<const float4*>(t);

    float acc = 0.0f;
    int stride = nblk * NTHR;
    for (int i = blockIdx.x * NTHR + threadIdx.x; i < n_vec; i += stride) {
        float4 sv = s4[i];
        float4 tv = t4[i];
        acc += tv.x * __logf(sv.x);
        acc += tv.y * __logf(sv.y);
        acc += tv.z * __logf(sv.z);
        acc += tv.w * __logf(sv.w);
    }
    if (blockIdx.x == 0) {
        for (int i = tail0 + threadIdx.x; i < n; i += NTHR)
            acc += t[i] * __logf(s[i]);
    }

    finish(acc, inv_B, out, nblk);
}

extern "C" void kernel_launch(void* const* d_in, const int* in_sizes, int n_in,
                              void* d_out, int out_size)
{
    const float* s = (const float*)d_in[0];  // preds_s
    const float* t = (const float*)d_in[1];  // preds_t
    float* out = (float*)d_out;

    int n = in_sizes[0];
    float inv_B = (n == 4096000) ? (1.0f / 4096.0f) : (1000.0f / (float)n);

    int n_vec = n / 4;

    if ((n % 4 == 0) && (n_vec == NBLK_EX * NST * NTHR)) {
        casync_reduce<<<NBLK_EX, NTHR>>>(
            reinterpret_cast<const float4*>(s),
            reinterpret_cast<const float4*>(t),
            inv_B, out);
    } else {
        int nblk = 1024;
        fused_reduce_generic<<<nblk, NTHR>>>(s, t, n, inv_B, out, nblk);
    }
}

// round 9
// speedup vs baseline: 1.0269x; 1.0269x over previous
#include <cuda_runtime.h>
#include <cuda_bf16.h>
#include <cstdint>

// -(1/B) * sum(preds_t * log(preds_s)),  B = 4096, C = 1000  (n = 4,096,000)
// 256-bit loads (ld.global.v8.f32, sm_100+): n = 512,000 v8-vectors per array
// = 1000 CTAs x 256 thr x 2 v8/thread exactly. All 4 v8 loads issued as
// asm volatile before any math -> guaranteed front-batched, 128B/thread in flight.

#define NTHR    256
#define NBLK_EX 1000
#define MAXBLK  2048

__device__ float g_partials[MAXBLK];
__device__ unsigned int g_ticket;   // zero-init; reset by last block each call

struct v8 { float f[8]; };

__device__ __forceinline__ void ldg_v8(v8& r, const float* p) {
    asm volatile(
        "ld.global.v8.f32 {%0, %1, %2, %3, %4, %5, %6, %7}, [%8];"
        : "=f"(r.f[0]), "=f"(r.f[1]), "=f"(r.f[2]), "=f"(r.f[3]),
          "=f"(r.f[4]), "=f"(r.f[5]), "=f"(r.f[6]), "=f"(r.f[7])
        : "l"(p));
}

__device__ __forceinline__ float block_reduce(float acc, float* warp_sums)
{
    #pragma unroll
    for (int off = 16; off > 0; off >>= 1)
        acc += __shfl_xor_sync(0xFFFFFFFFu, acc, off);

    int lane = threadIdx.x & 31;
    int wid  = threadIdx.x >> 5;
    if (lane == 0) warp_sums[wid] = acc;
    __syncthreads();

    float v = 0.0f;
    if (wid == 0) {
        v = (lane < NTHR / 32) ? warp_sums[lane] : 0.0f;
        #pragma unroll
        for (int off = 4; off > 0; off >>= 1)
            v += __shfl_xor_sync(0xFFFFFFFFu, v, off);
    }
    return v;   // valid in warp 0 lane 0
}

__device__ __forceinline__ void finish(float acc, float inv_B, float* out, int nblk)
{
    __shared__ float warp_sums[NTHR / 32];
    float bsum = block_reduce(acc, warp_sums);

    __shared__ bool is_last;
    if (threadIdx.x == 0) {
        g_partials[blockIdx.x] = bsum;
        __threadfence();
        unsigned int ticket = atomicAdd(&g_ticket, 1u);
        is_last = (ticket == (unsigned int)(nblk - 1));
    }
    __syncthreads();

    if (is_last) {
        float a = 0.0f;
        for (int i = threadIdx.x; i < nblk; i += NTHR)
            a += g_partials[i];
        __syncthreads();
        float total = block_reduce(a, warp_sums);
        if (threadIdx.x == 0) {
            out[0] = -total * inv_B;
            g_ticket = 0;                   // reset for next graph replay
        }
    }
}

__global__ __launch_bounds__(NTHR) void v8_reduce(
    const float* __restrict__ s, const float* __restrict__ t,
    float inv_B, float* __restrict__ out)
{
    // v8 element index for this thread; stride between its two vectors
    const long i0 = ((long)blockIdx.x * NTHR + threadIdx.x) * 8;
    const long stride8 = (long)NBLK_EX * NTHR * 8;     // 2,048,000 floats

    v8 s0, t0, s1, t1;
    // Four 256-bit loads, front-batched (asm volatile preserves order)
    ldg_v8(s0, s + i0);
    ldg_v8(t0, t + i0);
    ldg_v8(s1, s + i0 + stride8);
    ldg_v8(t1, t + i0 + stride8);

    float a0 = 0.0f, a1 = 0.0f;
    #pragma unroll
    for (int k = 0; k < 8; k++) a0 += t0.f[k] * __logf(s0.f[k]);
    #pragma unroll
    for (int k = 0; k < 8; k++) a1 += t1.f[k] * __logf(s1.f[k]);

    finish(a0 + a1, inv_B, out, NBLK_EX);
}

// Generic fallback (any n), grid-stride. Only used if shape isn't exact-cover.
__global__ __launch_bounds__(NTHR) void fused_reduce_generic(
    const float* __restrict__ s, const float* __restrict__ t,
    int n, float inv_B, float* __restrict__ out, int nblk)
{
    int n_vec = n / 4;
    int tail0 = n_vec * 4;
    const float4* s4 = reinterpret_cast<const float4*>(s);
    const float4* t4 = reinterpret_cast<const float4*>(t);

    float acc = 0.0f;
    int stride = nblk * NTHR;
    for (int i = blockIdx.x * NTHR + threadIdx.x; i < n_vec; i += stride) {
        float4 sv = s4[i];
        float4 tv = t4[i];
        acc += tv.x * __logf(sv.x);
        acc += tv.y * __logf(sv.y);
        acc += tv.z * __logf(sv.z);
        acc += tv.w * __logf(sv.w);
    }
    if (blockIdx.x == 0) {
        for (int i = tail0 + threadIdx.x; i < n; i += NTHR)
            acc += t[i] * __logf(s[i]);
    }

    finish(acc, inv_B, out, nblk);
}

extern "C" void kernel_launch(void* const* d_in, const int* in_sizes, int n_in,
                              void* d_out, int out_size)
{
    const float* s = (const float*)d_in[0];  // preds_s
    const float* t = (const float*)d_in[1];  // preds_t
    float* out = (float*)d_out;

    int n = in_sizes[0];
    float inv_B = (n == 4096000) ? (1.0f / 4096.0f) : (1000.0f / (float)n);

    // exact cover: 1000 blocks x 256 thr x 2 v8 = 4,096,000 floats per array
    if (n == NBLK_EX * NTHR * 16) {
        v8_reduce<<<NBLK_EX, NTHR>>>(s, t, inv_B, out);
    } else {
        int nblk = 1024;
        fused_reduce_generic<<<nblk, NTHR>>>(s, t, n, inv_B, out, nblk);
    }
}